// round 14
// baseline (speedup 1.0000x reference)
#include <cuda_runtime.h>
#include <mma.h>
#include <math.h>
#include <stdint.h>

using namespace nvcuda;

#define F_IN  512
#define H_DIM 256
#define W_DIM 64

// smem float offsets (A/B gemm kernels): sA 2x4352 | sB 2x4352 | bias tile 16x68
#define SM_AB_F  18496
#define SM_AB_BYTES (SM_AB_F * 4)            // 73984 B -> 3 CTAs/SM
// gemm3: + second tile + red/flg
#define SM_C_F   19596
#define SM_C_BYTES (SM_C_F * 4)              // 78384 B

static __device__ float g_Wtf[212992];       // W1|W2|Wq tf32-rounded
static __device__ float g_act1[8192 * 256];
static __device__ float g_act2[8192 * 256];
static __device__ float g_part[128];
static __device__ unsigned int g_cnt = 0;

__device__ __forceinline__ float f2tf(float f) {
    uint32_t r;
    asm("cvt.rna.tf32.f32 %0, %1;" : "=r"(r) : "f"(f));
    return __uint_as_float(r);
}
__device__ __forceinline__ void cpa16(uint32_t dst, const float* src) {
    asm volatile("cp.async.cg.shared.global [%0], [%1], 16;" :: "r"(dst), "l"(src));
}
#define CPA_COMMIT() asm volatile("cp.async.commit_group;" ::: "memory")
template<int N> __device__ __forceinline__ void cpa_wait() {
    asm volatile("cp.async.wait_group %0;" :: "n"(N) : "memory");
}

typedef wmma::fragment<wmma::matrix_a, 16, 16, 8, wmma::precision::tf32, wmma::row_major> FragA;
typedef wmma::fragment<wmma::matrix_b, 16, 16, 8, wmma::precision::tf32, wmma::row_major> FragB;
typedef wmma::fragment<wmma::accumulator, 16, 16, 8, float> FragC;

__global__ void conv_w(const float* __restrict__ W1, const float* __restrict__ W2,
                       const float* __restrict__ Wq)
{
    const int i = blockIdx.x * blockDim.x + threadIdx.x;
    if (i >= 53248) return;
    const float4* src;
    int off;
    if (i < 32768)      { src = (const float4*)W1; off = i; }
    else if (i < 49152) { src = (const float4*)W2; off = i - 32768; }
    else                { src = (const float4*)Wq; off = i - 49152; }
    float4 v = src[off];
    ((float4*)g_Wtf)[i] = make_float4(f2tf(v.x), f2tf(v.y), f2tf(v.z), f2tf(v.w));
}

// ---------- GEMM1: g_act1 = relu(X @ W1 + b1), M=8192 N=256 K=512 ----------
__global__ void __launch_bounds__(128, 3)
gemm1(const float* __restrict__ X, const float* __restrict__ b1)
{
    extern __shared__ float sm[];
    float* sA = sm;               // 2 x 64x68
    float* sB = sm + 8704;        // 2 x 64x68
    float* sT = sm + 17408;       // 16 x 68 bias tile
    const uint32_t sb32 = (uint32_t)__cvta_generic_to_shared(sm);

    const int t = threadIdx.x, w = t >> 5;
    const int mb = blockIdx.x >> 2, nb = blockIdx.x & 3;
    const int row0 = mb * 64, col0 = nb * 64;
    const int mw = w >> 1, nw = w & 1;
    const float* W1t = g_Wtf;

    if (t < 64) {
        const float v = b1[col0 + t];
        #pragma unroll
        for (int r = 0; r < 16; ++r) sT[r * 68 + t] = v;
    }

    float4 xr[8];
    auto ldgX = [&](int s) {
        #pragma unroll
        for (int q = 0; q < 8; ++q) {
            const int idx = t + q * 128;
            const int r = idx >> 4, c4 = idx & 15;
            xr[q] = *reinterpret_cast<const float4*>(X + (size_t)(row0 + r) * F_IN + s * 64 + c4 * 4);
        }
    };
    auto stsX = [&](int buf) {
        #pragma unroll
        for (int q = 0; q < 8; ++q) {
            const int idx = t + q * 128;
            const int r = idx >> 4, c4 = idx & 15;
            *reinterpret_cast<float4*>(sA + buf * 4352 + r * 68 + c4 * 4) =
                make_float4(f2tf(xr[q].x), f2tf(xr[q].y), f2tf(xr[q].z), f2tf(xr[q].w));
        }
    };
    auto fillB = [&](int s, int buf) {
        const uint32_t dst = sb32 + (8704 + buf * 4352) * 4;
        #pragma unroll
        for (int q = 0; q < 8; ++q) {
            const int idx = t + q * 128;
            const int r = idx >> 4, c4 = idx & 15;
            cpa16(dst + (r * 68 + c4 * 4) * 4, W1t + (size_t)(s * 64 + r) * H_DIM + col0 + c4 * 4);
        }
    };

    FragC acc[2][2];
    #pragma unroll
    for (int i = 0; i < 2; ++i)
        #pragma unroll
        for (int j = 0; j < 2; ++j) wmma::fill_fragment(acc[i][j], 0.0f);

    ldgX(0); stsX(0); fillB(0, 0); CPA_COMMIT();
    for (int s = 0; s < 8; ++s) {
        const int cb = s & 1;
        cpa_wait<0>();
        __syncthreads();
        if (s < 7) { ldgX(s + 1); fillB(s + 1, cb ^ 1); CPA_COMMIT(); }
        const float* ax = sA + cb * 4352;
        const float* bx = sB + cb * 4352;
        #pragma unroll
        for (int kk = 0; kk < 64; kk += 8) {
            FragA a[2];
            wmma::load_matrix_sync(a[0], ax + (2 * mw + 0) * 16 * 68 + kk, 68);
            wmma::load_matrix_sync(a[1], ax + (2 * mw + 1) * 16 * 68 + kk, 68);
            FragB b[2];
            wmma::load_matrix_sync(b[0], bx + kk * 68 + (2 * nw + 0) * 16, 68);
            wmma::load_matrix_sync(b[1], bx + kk * 68 + (2 * nw + 1) * 16, 68);
            #pragma unroll
            for (int i = 0; i < 2; ++i)
                #pragma unroll
                for (int j = 0; j < 2; ++j)
                    wmma::mma_sync(acc[i][j], a[i], b[j], acc[i][j]);
        }
        if (s < 7) stsX(cb ^ 1);
    }
    #pragma unroll
    for (int j = 0; j < 2; ++j) {
        FragC bf;
        wmma::load_matrix_sync(bf, sT + (2 * nw + j) * 16, 68, wmma::mem_row_major);
        #pragma unroll
        for (int i = 0; i < 2; ++i) {
            #pragma unroll
            for (int e = 0; e < bf.num_elements; ++e)
                acc[i][j].x[e] = f2tf(fmaxf(acc[i][j].x[e] + bf.x[e], 0.0f));
            wmma::store_matrix_sync(g_act1 + (size_t)(row0 + (2 * mw + i) * 16) * H_DIM
                                    + col0 + (2 * nw + j) * 16,
                                    acc[i][j], H_DIM, wmma::mem_row_major);
        }
    }
}

// ---------- GEMM2: g_act2 = relu(g_act1 @ W2 + b2), M=8192 N=256 K=256 ----------
__global__ void __launch_bounds__(128, 3)
gemm2(const float* __restrict__ b2)
{
    extern __shared__ float sm[];
    float* sA = sm;
    float* sB = sm + 8704;
    float* sT = sm + 17408;
    const uint32_t sb32 = (uint32_t)__cvta_generic_to_shared(sm);

    const int t = threadIdx.x, w = t >> 5;
    const int mb = blockIdx.x >> 2, nb = blockIdx.x & 3;
    const int row0 = mb * 64, col0 = nb * 64;
    const int mw = w >> 1, nw = w & 1;
    const float* W2t = g_Wtf + 131072;

    if (t < 64) {
        const float v = b2[col0 + t];
        #pragma unroll
        for (int r = 0; r < 16; ++r) sT[r * 68 + t] = v;
    }

    auto fillA = [&](int s, int buf) {
        const uint32_t dst = sb32 + (buf * 4352) * 4;
        #pragma unroll
        for (int q = 0; q < 8; ++q) {
            const int idx = t + q * 128;
            const int r = idx >> 4, c4 = idx & 15;
            cpa16(dst + (r * 68 + c4 * 4) * 4, g_act1 + (size_t)(row0 + r) * H_DIM + s * 64 + c4 * 4);
        }
    };
    auto fillB = [&](int s, int buf) {
        const uint32_t dst = sb32 + (8704 + buf * 4352) * 4;
        #pragma unroll
        for (int q = 0; q < 8; ++q) {
            const int idx = t + q * 128;
            const int r = idx >> 4, c4 = idx & 15;
            cpa16(dst + (r * 68 + c4 * 4) * 4, W2t + (size_t)(s * 64 + r) * H_DIM + col0 + c4 * 4);
        }
    };

    FragC acc[2][2];
    #pragma unroll
    for (int i = 0; i < 2; ++i)
        #pragma unroll
        for (int j = 0; j < 2; ++j) wmma::fill_fragment(acc[i][j], 0.0f);

    fillA(0, 0); fillB(0, 0); CPA_COMMIT();
    for (int s = 0; s < 4; ++s) {
        const int cb = s & 1;
        cpa_wait<0>();
        __syncthreads();
        if (s < 3) { fillA(s + 1, cb ^ 1); fillB(s + 1, cb ^ 1); CPA_COMMIT(); }
        const float* ax = sA + cb * 4352;
        const float* bx = sB + cb * 4352;
        #pragma unroll
        for (int kk = 0; kk < 64; kk += 8) {
            FragA a[2];
            wmma::load_matrix_sync(a[0], ax + (2 * mw + 0) * 16 * 68 + kk, 68);
            wmma::load_matrix_sync(a[1], ax + (2 * mw + 1) * 16 * 68 + kk, 68);
            FragB b[2];
            wmma::load_matrix_sync(b[0], bx + kk * 68 + (2 * nw + 0) * 16, 68);
            wmma::load_matrix_sync(b[1], bx + kk * 68 + (2 * nw + 1) * 16, 68);
            #pragma unroll
            for (int i = 0; i < 2; ++i)
                #pragma unroll
                for (int j = 0; j < 2; ++j)
                    wmma::mma_sync(acc[i][j], a[i], b[j], acc[i][j]);
        }
    }
    #pragma unroll
    for (int j = 0; j < 2; ++j) {
        FragC bf;
        wmma::load_matrix_sync(bf, sT + (2 * nw + j) * 16, 68, wmma::mem_row_major);
        #pragma unroll
        for (int i = 0; i < 2; ++i) {
            #pragma unroll
            for (int e = 0; e < bf.num_elements; ++e)
                acc[i][j].x[e] = f2tf(fmaxf(acc[i][j].x[e] + bf.x[e], 0.0f));
            wmma::store_matrix_sync(g_act2 + (size_t)(row0 + (2 * mw + i) * 16) * H_DIM
                                    + col0 + (2 * nw + j) * 16,
                                    acc[i][j], H_DIM, wmma::mem_row_major);
        }
    }
}

// ---------- GEMM3 + reduce: out = sum tanh(g_act2 @ Wq + bq) * Wh + bh ----------
__global__ void __launch_bounds__(128, 1)
gemm3(const float* __restrict__ bq, const float* __restrict__ Wh,
      const float* __restrict__ bh, float* __restrict__ out)
{
    extern __shared__ float sm[];
    float* sA  = sm;
    float* sB  = sm + 8704;
    float* sT  = sm + 17408;      // bq tile 16x68
    float* sT2 = sm + 18496;      // wh tile 16x68
    float* red = sm + 19584;      // 4 warp partials
    float* flg = sm + 19588;
    const uint32_t sb32 = (uint32_t)__cvta_generic_to_shared(sm);

    const int t = threadIdx.x, w = t >> 5;
    const int row0 = blockIdx.x * 64;
    const int mw = w >> 1, nw = w & 1;
    const float* Wqt = g_Wtf + 196608;

    if (t < 64) {
        const float vq = bq[t], vw = Wh[t];
        #pragma unroll
        for (int r = 0; r < 16; ++r) { sT[r * 68 + t] = vq; sT2[r * 68 + t] = vw; }
    }

    auto fillA = [&](int s, int buf) {
        const uint32_t dst = sb32 + (buf * 4352) * 4;
        #pragma unroll
        for (int q = 0; q < 8; ++q) {
            const int idx = t + q * 128;
            const int r = idx >> 4, c4 = idx & 15;
            cpa16(dst + (r * 68 + c4 * 4) * 4, g_act2 + (size_t)(row0 + r) * H_DIM + s * 64 + c4 * 4);
        }
    };
    auto fillB = [&](int s, int buf) {
        const uint32_t dst = sb32 + (8704 + buf * 4352) * 4;
        #pragma unroll
        for (int q = 0; q < 8; ++q) {
            const int idx = t + q * 128;
            const int r = idx >> 4, c4 = idx & 15;
            cpa16(dst + (r * 68 + c4 * 4) * 4, Wqt + (size_t)(s * 64 + r) * W_DIM + c4 * 4);
        }
    };

    FragC acc[2][2];
    #pragma unroll
    for (int i = 0; i < 2; ++i)
        #pragma unroll
        for (int j = 0; j < 2; ++j) wmma::fill_fragment(acc[i][j], 0.0f);

    fillA(0, 0); fillB(0, 0); CPA_COMMIT();
    for (int s = 0; s < 4; ++s) {
        const int cb = s & 1;
        cpa_wait<0>();
        __syncthreads();
        if (s < 3) { fillA(s + 1, cb ^ 1); fillB(s + 1, cb ^ 1); CPA_COMMIT(); }
        const float* ax = sA + cb * 4352;
        const float* bx = sB + cb * 4352;
        #pragma unroll
        for (int kk = 0; kk < 64; kk += 8) {
            FragA a[2];
            wmma::load_matrix_sync(a[0], ax + (2 * mw + 0) * 16 * 68 + kk, 68);
            wmma::load_matrix_sync(a[1], ax + (2 * mw + 1) * 16 * 68 + kk, 68);
            FragB b[2];
            wmma::load_matrix_sync(b[0], bx + kk * 68 + (2 * nw + 0) * 16, 68);
            wmma::load_matrix_sync(b[1], bx + kk * 68 + (2 * nw + 1) * 16, 68);
            #pragma unroll
            for (int i = 0; i < 2; ++i)
                #pragma unroll
                for (int j = 0; j < 2; ++j)
                    wmma::mma_sync(acc[i][j], a[i], b[j], acc[i][j]);
        }
    }

    float p = 0.0f;
    #pragma unroll
    for (int j = 0; j < 2; ++j) {
        FragC bqf, whf;
        wmma::load_matrix_sync(bqf, sT  + (2 * nw + j) * 16, 68, wmma::mem_row_major);
        wmma::load_matrix_sync(whf, sT2 + (2 * nw + j) * 16, 68, wmma::mem_row_major);
        #pragma unroll
        for (int i = 0; i < 2; ++i)
            #pragma unroll
            for (int e = 0; e < bqf.num_elements; ++e)
                p += tanhf(acc[i][j].x[e] + bqf.x[e]) * whf.x[e];
    }
    #pragma unroll
    for (int off = 16; off > 0; off >>= 1)
        p += __shfl_down_sync(0xffffffffu, p, off);
    if ((t & 31) == 0) red[w] = p;
    __syncthreads();
    if (t == 0) {
        g_part[blockIdx.x] = (red[0] + red[1]) + (red[2] + red[3]);
        __threadfence();
        unsigned int v = atomicAdd(&g_cnt, 1u);
        flg[0] = (v == 127u) ? 1.0f : 0.0f;
    }
    __syncthreads();

    if (flg[0] != 0.0f) {
        __threadfence();
        float v = g_part[t];
        #pragma unroll
        for (int off = 16; off > 0; off >>= 1)
            v += __shfl_down_sync(0xffffffffu, v, off);
        if ((t & 31) == 0) red[w] = v;
        __syncthreads();
        if (t == 0) {
            out[0] = (red[0] + red[1]) + (red[2] + red[3]) + bh[0];
            g_cnt = 0;
        }
    }
}

extern "C" void kernel_launch(void* const* d_in, const int* in_sizes, int n_in,
                              void* d_out, int out_size)
{
    const float* X  = (const float*)d_in[0];
    const float* W1 = (const float*)d_in[1];
    const float* b1 = (const float*)d_in[2];
    const float* W2 = (const float*)d_in[3];
    const float* b2 = (const float*)d_in[4];
    const float* Wq = (const float*)d_in[5];
    const float* bq = (const float*)d_in[6];
    const float* Wh = (const float*)d_in[7];
    const float* bh = (const float*)d_in[8];

    cudaFuncSetAttribute(gemm1, cudaFuncAttributeMaxDynamicSharedMemorySize, SM_AB_BYTES);
    cudaFuncSetAttribute(gemm2, cudaFuncAttributeMaxDynamicSharedMemorySize, SM_AB_BYTES);
    cudaFuncSetAttribute(gemm3, cudaFuncAttributeMaxDynamicSharedMemorySize, SM_C_BYTES);

    conv_w<<<208, 256>>>(W1, W2, Wq);
    gemm1<<<512, 128, SM_AB_BYTES>>>(X, b1);
    gemm2<<<512, 128, SM_AB_BYTES>>>(b2);
    gemm3<<<128, 128, SM_C_BYTES>>>(bq, Wh, bh, (float*)d_out);
}

// round 15
// speedup vs baseline: 2.4493x; 2.4493x over previous
#include <cuda_runtime.h>
#include <math.h>
#include <stdint.h>

#define NBLK    128
#define THREADS 256
#define F_IN    512
#define H_DIM   256
#define W_DIM   64

// smem float offsets
#define O_ACT  0            // 128 A-frags * 132 = 16896 (X 2-bufs 2*4224 alias front)
#define O_B    16896        // 2 B slabs * 16384
#define O_C    49664        // b1(256) b2(256) bq(64) wh(64) red(8) flg(1)
#define SMEMF  50316
#define SMEM_BYTES (SMEMF * 4)   // 201264 B -> 1 CTA/SM

static __device__ float g_Wf[212992];   // W1|W2|Wq, tf32-rounded, FRAGMENT-MAJOR
static __device__ float g_part[NBLK];
static __device__ unsigned int g_cnt = 0;

__device__ __forceinline__ float f2tf(float f) {
    uint32_t r;
    asm("cvt.rna.tf32.f32 %0, %1;" : "=r"(r) : "f"(f));
    return __uint_as_float(r);
}
__device__ __forceinline__ void cpa16(uint32_t dst, const float* src) {
    asm volatile("cp.async.cg.shared.global [%0], [%1], 16;" :: "r"(dst), "l"(src));
}
#define CPA_COMMIT() asm volatile("cp.async.commit_group;" ::: "memory")
template<int N> __device__ __forceinline__ void cpa_wait() {
    asm volatile("cp.async.wait_group %0;" :: "n"(N) : "memory");
}
// D(16x8) += A(16x8,row) * B(8x8,col)   tf32
__device__ __forceinline__ void mma8(float* d, const uint4& a, uint32_t b0, uint32_t b1) {
    asm volatile("mma.sync.aligned.m16n8k8.row.col.f32.tf32.tf32.f32 "
                 "{%0,%1,%2,%3}, {%4,%5,%6,%7}, {%8,%9}, {%0,%1,%2,%3};"
                 : "+f"(d[0]), "+f"(d[1]), "+f"(d[2]), "+f"(d[3])
                 : "r"(a.x), "r"(a.y), "r"(a.z), "r"(a.w), "r"(b0), "r"(b1));
}

// conv_w: tf32-round weights AND permute to fragment-major B layout.
// out index: ((kt*NT + nt)*32 + g*4 + tg)*4 + half*2 + bb
//   kt=k>>3, rr=k&7, tg=rr&3, bb=rr>>2; nt=c>>4, w16=c&15, g=w16&7, half=w16>>3
__global__ void conv_w(const float* __restrict__ W1, const float* __restrict__ W2,
                       const float* __restrict__ Wq)
{
    const int i = blockIdx.x * blockDim.x + threadIdx.x;
    if (i >= 53248) return;
    const float4* src; int off, base, NT, k, c;
    if (i < 32768)      { src = (const float4*)W1; off = i;          base = 0;      NT = 16; k = off >> 6; c = (off & 63) * 4; }
    else if (i < 49152) { src = (const float4*)W2; off = i - 32768;  base = 131072; NT = 16; k = off >> 6; c = (off & 63) * 4; }
    else                { src = (const float4*)Wq; off = i - 49152;  base = 196608; NT = 4;  k = off >> 4; c = (off & 15) * 4; }
    float4 v = src[off];
    float vv[4] = { v.x, v.y, v.z, v.w };
    const int kt = k >> 3, rr = k & 7, tg = rr & 3, bb = rr >> 2;
    #pragma unroll
    for (int e = 0; e < 4; ++e) {
        const int cc = c + e, nt = cc >> 4, w16 = cc & 15, g = w16 & 7, hf = w16 >> 3;
        g_Wf[base + ((kt * NT + nt) * 32 + g * 4 + tg) * 4 + hf * 2 + bb] = f2tf(vv[e]);
    }
}

__global__ void __launch_bounds__(THREADS, 1)
fused_mma(const float* __restrict__ X,
          const float* __restrict__ b1, const float* __restrict__ b2,
          const float* __restrict__ bq, const float* __restrict__ Wh,
          const float* __restrict__ bh, float* __restrict__ out)
{
    extern __shared__ float sm[];
    float* sAct = sm;
    float* sB   = sm + O_B;
    float* b1s  = sm + O_C;
    float* b2s  = b1s + 256;
    float* bqs  = b2s + 256;
    float* whs  = bqs + 64;
    float* red  = whs + 64;
    float* flg  = red + 8;
    const uint32_t sb32 = (uint32_t)__cvta_generic_to_shared(sm);

    const int t = threadIdx.x;
    const int w = t >> 5, lane = t & 31;
    const int g = lane >> 2, tg = lane & 3;
    const int row0 = blockIdx.x * 64;
    const int mg = w >> 2, ng = w & 3;           // L1/L2 warp tile: m32 x n64

    b1s[t] = b1[t];
    b2s[t] = b2[t];
    if (t < 64) { bqs[t] = bq[t]; whs[t] = Wh[t]; }

    const float* W1f = g_Wf;
    const float* W2f = g_Wf + 131072;
    const float* Wqf = g_Wf + 196608;

    // X slab 64x64 -> fragment-major (fragIdx = mt*8+ktL, stride 132), tf32-rounded
    auto fillX = [&](int s, int buf) {
        #pragma unroll
        for (int q = 0; q < 4; ++q) {
            const int idx = t + q * 256;          // 0..1023 f4
            const int r = idx >> 4, c4 = idx & 15;
            float4 v = *reinterpret_cast<const float4*>(X + (size_t)(row0 + r) * F_IN + s * 64 + c4 * 4);
            float vv[4] = { v.x, v.y, v.z, v.w };
            const int mt = r >> 4, gg = r & 7, rowH = (r >> 3) & 1;
            const int ktL = c4 >> 1, i0 = (c4 & 1) * 2 + rowH;
            float* dst = sm + buf * 4224 + (mt * 8 + ktL) * 132 + gg * 16 + i0;
            #pragma unroll
            for (int e = 0; e < 4; ++e) dst[e * 4] = f2tf(vv[e]);
        }
    };
    // weight slab: linear cp.async of pre-permuted global
    auto fillB = [&](const float* __restrict__ src, int nf4, int buf) {
        const uint32_t dst = sb32 + (O_B + buf * 16384) * 4;
        #pragma unroll
        for (int q = 0; q < 16; ++q) {
            const int idx = t + q * 256;
            if (idx < nf4) cpa16(dst + idx * 16, src + idx * 4);
        }
    };

    float acc[2][8][4];
    #pragma unroll
    for (int i = 0; i < 2; ++i)
        #pragma unroll
        for (int jj = 0; jj < 8; ++jj)
            #pragma unroll
            for (int e = 0; e < 4; ++e) acc[i][jj][e] = 0.0f;

    // ============ Layer 1: K=512, 8 slabs of 64 ============
    fillX(0, 0); fillB(W1f, 4096, 0); CPA_COMMIT();
    for (int s = 0; s < 8; ++s) {
        const int cb = s & 1;
        cpa_wait<0>();
        __syncthreads();
        if (s < 7) { fillX(s + 1, cb ^ 1); fillB(W1f + (s + 1) * 16384, 4096, cb ^ 1); CPA_COMMIT(); }
        const float* ax = sm + cb * 4224;
        const float* bx = sB + cb * 16384;
        #pragma unroll
        for (int kk = 0; kk < 8; ++kk) {
            uint4 a0 = *reinterpret_cast<const uint4*>(ax + ((mg * 2 + 0) * 8 + kk) * 132 + lane * 4);
            uint4 a1 = *reinterpret_cast<const uint4*>(ax + ((mg * 2 + 1) * 8 + kk) * 132 + lane * 4);
            #pragma unroll
            for (int j = 0; j < 4; ++j) {
                uint4 bq4 = *reinterpret_cast<const uint4*>(bx + (kk * 16 + ng * 4 + j) * 128 + lane * 4);
                mma8(acc[0][2 * j + 0], a0, bq4.x, bq4.y);
                mma8(acc[0][2 * j + 1], a0, bq4.z, bq4.w);
                mma8(acc[1][2 * j + 0], a1, bq4.x, bq4.y);
                mma8(acc[1][2 * j + 1], a1, bq4.z, bq4.w);
            }
        }
    }
    // ---- boundary 1: bias+relu+round, store into act A-frag layout ----
    __syncthreads();
    fillB(W2f, 4096, 0); CPA_COMMIT();
    {
        const int offC0 = g * 16 + ((2 * tg) & 3) * 4 + ((tg >= 2) ? 2 : 0);
        const int offC1 = g * 16 + ((2 * tg + 1) & 3) * 4 + ((tg >= 2) ? 2 : 0);
        #pragma unroll
        for (int i = 0; i < 2; ++i) {
            const int mt = mg * 2 + i;
            #pragma unroll
            for (int jj = 0; jj < 8; ++jj) {
                const int kt = ng * 8 + jj;
                const int col0 = ng * 64 + jj * 8 + 2 * tg;
                float* base = sAct + (mt * 32 + kt) * 132;
                const float bA = b1s[col0], bB = b1s[col0 + 1];
                float v0 = f2tf(fmaxf(acc[i][jj][0] + bA, 0.0f));
                float v2 = f2tf(fmaxf(acc[i][jj][2] + bA, 0.0f));
                float v1 = f2tf(fmaxf(acc[i][jj][1] + bB, 0.0f));
                float v3 = f2tf(fmaxf(acc[i][jj][3] + bB, 0.0f));
                *reinterpret_cast<float2*>(base + offC0) = make_float2(v0, v2);
                *reinterpret_cast<float2*>(base + offC1) = make_float2(v1, v3);
            }
        }
    }

    // ============ Layer 2: K=256, 4 slabs ============
    #pragma unroll
    for (int i = 0; i < 2; ++i)
        #pragma unroll
        for (int jj = 0; jj < 8; ++jj)
            #pragma unroll
            for (int e = 0; e < 4; ++e) acc[i][jj][e] = 0.0f;
    for (int s = 0; s < 4; ++s) {
        const int cb = s & 1;
        cpa_wait<0>();
        __syncthreads();                          // publishes boundary-1 stores at s==0
        if (s < 3) { fillB(W2f + (s + 1) * 16384, 4096, cb ^ 1); CPA_COMMIT(); }
        const float* bx = sB + cb * 16384;
        #pragma unroll
        for (int kk = 0; kk < 8; ++kk) {
            uint4 a0 = *reinterpret_cast<const uint4*>(sAct + ((mg * 2 + 0) * 32 + s * 8 + kk) * 132 + lane * 4);
            uint4 a1 = *reinterpret_cast<const uint4*>(sAct + ((mg * 2 + 1) * 32 + s * 8 + kk) * 132 + lane * 4);
            #pragma unroll
            for (int j = 0; j < 4; ++j) {
                uint4 bq4 = *reinterpret_cast<const uint4*>(bx + (kk * 16 + ng * 4 + j) * 128 + lane * 4);
                mma8(acc[0][2 * j + 0], a0, bq4.x, bq4.y);
                mma8(acc[0][2 * j + 1], a0, bq4.z, bq4.w);
                mma8(acc[1][2 * j + 0], a1, bq4.x, bq4.y);
                mma8(acc[1][2 * j + 1], a1, bq4.z, bq4.w);
            }
        }
    }
    // ---- boundary 2: bias+relu+round, store act2 in place ----
    __syncthreads();
    fillB(Wqf, 1024, 0); CPA_COMMIT();
    {
        const int offC0 = g * 16 + ((2 * tg) & 3) * 4 + ((tg >= 2) ? 2 : 0);
        const int offC1 = g * 16 + ((2 * tg + 1) & 3) * 4 + ((tg >= 2) ? 2 : 0);
        #pragma unroll
        for (int i = 0; i < 2; ++i) {
            const int mt = mg * 2 + i;
            #pragma unroll
            for (int jj = 0; jj < 8; ++jj) {
                const int kt = ng * 8 + jj;
                const int col0 = ng * 64 + jj * 8 + 2 * tg;
                float* base = sAct + (mt * 32 + kt) * 132;
                const float bA = b2s[col0], bB = b2s[col0 + 1];
                float v0 = f2tf(fmaxf(acc[i][jj][0] + bA, 0.0f));
                float v2 = f2tf(fmaxf(acc[i][jj][2] + bA, 0.0f));
                float v1 = f2tf(fmaxf(acc[i][jj][1] + bB, 0.0f));
                float v3 = f2tf(fmaxf(acc[i][jj][3] + bB, 0.0f));
                *reinterpret_cast<float2*>(base + offC0) = make_float2(v0, v2);
                *reinterpret_cast<float2*>(base + offC1) = make_float2(v1, v3);
            }
        }
    }

    // ============ Layer 3: K=256, 4 slabs, N=64; warp tile m16 x n32 ============
    const int mi3 = w >> 1, nh3 = w & 1;
    float acc3[4][4];
    #pragma unroll
    for (int jj = 0; jj < 4; ++jj)
        #pragma unroll
        for (int e = 0; e < 4; ++e) acc3[jj][e] = 0.0f;
    for (int s = 0; s < 4; ++s) {
        const int cb = s & 1;
        cpa_wait<0>();
        __syncthreads();                          // publishes boundary-2 stores at s==0
        if (s < 3) { fillB(Wqf + (s + 1) * 4096, 1024, cb ^ 1); CPA_COMMIT(); }
        const float* bx = sB + cb * 16384;
        #pragma unroll
        for (int kk = 0; kk < 8; ++kk) {
            uint4 a = *reinterpret_cast<const uint4*>(sAct + (mi3 * 32 + s * 8 + kk) * 132 + lane * 4);
            #pragma unroll
            for (int nt2 = 0; nt2 < 2; ++nt2) {
                uint4 bq4 = *reinterpret_cast<const uint4*>(bx + (kk * 4 + nh3 * 2 + nt2) * 128 + lane * 4);
                mma8(acc3[nt2 * 2 + 0], a, bq4.x, bq4.y);
                mma8(acc3[nt2 * 2 + 1], a, bq4.z, bq4.w);
            }
        }
    }

    // ---- Epilogue: p = sum tanh(C3 + bq)*Wh ----
    float p = 0.0f;
    #pragma unroll
    for (int nt2 = 0; nt2 < 2; ++nt2)
        #pragma unroll
        for (int h = 0; h < 2; ++h) {
            const int col0 = (nh3 * 2 + nt2) * 16 + h * 8 + 2 * tg;
            const float* d = acc3[nt2 * 2 + h];
            p += tanhf(d[0] + bqs[col0]) * whs[col0];
            p += tanhf(d[2] + bqs[col0]) * whs[col0];
            p += tanhf(d[1] + bqs[col0 + 1]) * whs[col0 + 1];
            p += tanhf(d[3] + bqs[col0 + 1]) * whs[col0 + 1];
        }
    #pragma unroll
    for (int off = 16; off > 0; off >>= 1)
        p += __shfl_down_sync(0xffffffffu, p, off);
    __syncthreads();
    if ((t & 31) == 0) red[w] = p;
    __syncthreads();
    if (t == 0) {
        float s = 0.0f;
        #pragma unroll
        for (int i = 0; i < 8; ++i) s += red[i];
        g_part[blockIdx.x] = s;
        __threadfence();
        unsigned int v = atomicAdd(&g_cnt, 1u);
        flg[0] = (v == NBLK - 1) ? 1.0f : 0.0f;
    }
    __syncthreads();

    if (flg[0] != 0.0f) {
        __threadfence();
        float v = 0.0f;
        if (t < 128) v = g_part[t];
        #pragma unroll
        for (int off = 16; off > 0; off >>= 1)
            v += __shfl_down_sync(0xffffffffu, v, off);
        if ((t & 31) == 0) red[w] = v;
        __syncthreads();
        if (t == 0) {
            out[0] = (red[0] + red[1]) + (red[2] + red[3]) + bh[0];
            g_cnt = 0;
        }
    }
}

extern "C" void kernel_launch(void* const* d_in, const int* in_sizes, int n_in,
                              void* d_out, int out_size)
{
    const float* X  = (const float*)d_in[0];
    const float* W1 = (const float*)d_in[1];
    const float* b1 = (const float*)d_in[2];
    const float* W2 = (const float*)d_in[3];
    const float* b2 = (const float*)d_in[4];
    const float* Wq = (const float*)d_in[5];
    const float* bq = (const float*)d_in[6];
    const float* Wh = (const float*)d_in[7];
    const float* bh = (const float*)d_in[8];

    conv_w<<<208, 256>>>(W1, W2, Wq);
    cudaFuncSetAttribute(fused_mma, cudaFuncAttributeMaxDynamicSharedMemorySize, SMEM_BYTES);
    fused_mma<<<NBLK, THREADS, SMEM_BYTES>>>(X, b1, b2, bq, Wh, bh, (float*)d_out);
}

// round 16
// speedup vs baseline: 2.4680x; 1.0076x over previous
#include <cuda_runtime.h>
#include <math.h>
#include <stdint.h>

#define NBLK    128
#define THREADS 256
#define F_IN    512
#define H_DIM   256
#define W_DIM   64

// smem float offsets
#define O_ACT  0            // 128 A-frags * 132 = 16896 (X 2-bufs 2*4224 alias front)
#define O_B    16896        // 2 B slabs * 16384
#define O_C    49664        // b1(256) b2(256) bq(64) wh(64) red(8) flg(1)
#define SMEMF  50316
#define SMEM_BYTES (SMEMF * 4)   // 201264 B -> 1 CTA/SM

static __device__ float g_Wf[212992];   // W1|W2|Wq, tf32-rounded, FRAGMENT-MAJOR
static __device__ float g_part[NBLK];
static __device__ unsigned int g_cnt = 0;

__device__ __forceinline__ float f2tf(float f) {
    uint32_t r;
    asm("cvt.rna.tf32.f32 %0, %1;" : "=r"(r) : "f"(f));
    return __uint_as_float(r);
}
__device__ __forceinline__ void cpa16(uint32_t dst, const float* src) {
    asm volatile("cp.async.cg.shared.global [%0], [%1], 16;" :: "r"(dst), "l"(src));
}
#define CPA_COMMIT() asm volatile("cp.async.commit_group;" ::: "memory")
template<int N> __device__ __forceinline__ void cpa_wait() {
    asm volatile("cp.async.wait_group %0;" :: "n"(N) : "memory");
}
// D(16x8) += A(16x8,row) * B(8x8,col)   tf32
__device__ __forceinline__ void mma8(float* d, const uint4& a, uint32_t b0, uint32_t b1) {
    asm volatile("mma.sync.aligned.m16n8k8.row.col.f32.tf32.tf32.f32 "
                 "{%0,%1,%2,%3}, {%4,%5,%6,%7}, {%8,%9}, {%0,%1,%2,%3};"
                 : "+f"(d[0]), "+f"(d[1]), "+f"(d[2]), "+f"(d[3])
                 : "r"(a.x), "r"(a.y), "r"(a.z), "r"(a.w), "r"(b0), "r"(b1));
}

// conv_w: tf32-round weights AND permute to fragment-major B layout.
__global__ void conv_w(const float* __restrict__ W1, const float* __restrict__ W2,
                       const float* __restrict__ Wq)
{
    const int i = blockIdx.x * blockDim.x + threadIdx.x;
    if (i >= 53248) return;
    const float4* src; int off, base, NT, k, c;
    if (i < 32768)      { src = (const float4*)W1; off = i;          base = 0;      NT = 16; k = off >> 6; c = (off & 63) * 4; }
    else if (i < 49152) { src = (const float4*)W2; off = i - 32768;  base = 131072; NT = 16; k = off >> 6; c = (off & 63) * 4; }
    else                { src = (const float4*)Wq; off = i - 49152;  base = 196608; NT = 4;  k = off >> 4; c = (off & 15) * 4; }
    float4 v = src[off];
    float vv[4] = { v.x, v.y, v.z, v.w };
    const int kt = k >> 3, rr = k & 7, tg = rr & 3, bb = rr >> 2;
    #pragma unroll
    for (int e = 0; e < 4; ++e) {
        const int cc = c + e, nt = cc >> 4, w16 = cc & 15, g = w16 & 7, hf = w16 >> 3;
        g_Wf[base + ((kt * NT + nt) * 32 + g * 4 + tg) * 4 + hf * 2 + bb] = f2tf(vv[e]);
    }
}

__global__ void __launch_bounds__(THREADS, 1)
fused_mma(const float* __restrict__ X,
          const float* __restrict__ b1, const float* __restrict__ b2,
          const float* __restrict__ bq, const float* __restrict__ Wh,
          const float* __restrict__ bh, float* __restrict__ out)
{
    extern __shared__ float sm[];
    float* sAct = sm;
    float* sB   = sm + O_B;
    float* b1s  = sm + O_C;
    float* b2s  = b1s + 256;
    float* bqs  = b2s + 256;
    float* whs  = bqs + 64;
    float* red  = whs + 64;
    float* flg  = red + 8;
    const uint32_t sb32 = (uint32_t)__cvta_generic_to_shared(sm);

    const int t = threadIdx.x;
    const int w = t >> 5, lane = t & 31;
    const int g = lane >> 2, tg = lane & 3;
    const int row0 = blockIdx.x * 64;
    const int mg = w >> 2, ng = w & 3;           // L1/L2 warp tile: m32 x n64

    b1s[t] = b1[t];
    b2s[t] = b2[t];
    if (t < 64) { bqs[t] = bq[t]; whs[t] = Wh[t]; }

    const float* W1f = g_Wf;
    const float* W2f = g_Wf + 131072;
    const float* Wqf = g_Wf + 196608;

    // X slab 64x64 -> fragment-major (fragIdx = mt*8+ktL, stride 132), tf32-rounded
    auto fillX = [&](int s, int buf) {
        #pragma unroll
        for (int q = 0; q < 4; ++q) {
            const int idx = t + q * 256;          // 0..1023 f4
            const int r = idx >> 4, c4 = idx & 15;
            float4 v = *reinterpret_cast<const float4*>(X + (size_t)(row0 + r) * F_IN + s * 64 + c4 * 4);
            float vv[4] = { v.x, v.y, v.z, v.w };
            const int mt = r >> 4, gg = r & 7, rowH = (r >> 3) & 1;
            const int ktL = c4 >> 1, i0 = (c4 & 1) * 2 + rowH;
            float* dst = sm + buf * 4224 + (mt * 8 + ktL) * 132 + gg * 16 + i0;
            #pragma unroll
            for (int e = 0; e < 4; ++e) dst[e * 4] = f2tf(vv[e]);
        }
    };
    // weight slab: linear cp.async of pre-permuted global
    auto fillB = [&](const float* __restrict__ src, int nf4, int buf) {
        const uint32_t dst = sb32 + (O_B + buf * 16384) * 4;
        #pragma unroll
        for (int q = 0; q < 16; ++q) {
            const int idx = t + q * 256;
            if (idx < nf4) cpa16(dst + idx * 16, src + idx * 4);
        }
    };

    float acc[2][8][4];
    #pragma unroll
    for (int i = 0; i < 2; ++i)
        #pragma unroll
        for (int jj = 0; jj < 8; ++jj)
            #pragma unroll
            for (int e = 0; e < 4; ++e) acc[i][jj][e] = 0.0f;

    // ============ Layer 1: K=512, 8 slabs of 64 ============
    fillX(0, 0); fillB(W1f, 4096, 0); CPA_COMMIT();
    for (int s = 0; s < 8; ++s) {
        const int cb = s & 1;
        cpa_wait<0>();
        __syncthreads();
        if (s < 7) { fillX(s + 1, cb ^ 1); fillB(W1f + (s + 1) * 16384, 4096, cb ^ 1); CPA_COMMIT(); }
        const float* ax = sm + cb * 4224;
        const float* bx = sB + cb * 16384;
        // register pipeline over kk
        uint4 a0 = *reinterpret_cast<const uint4*>(ax + ((mg * 2 + 0) * 8 + 0) * 132 + lane * 4);
        uint4 a1 = *reinterpret_cast<const uint4*>(ax + ((mg * 2 + 1) * 8 + 0) * 132 + lane * 4);
        uint4 bf[4];
        #pragma unroll
        for (int j = 0; j < 4; ++j)
            bf[j] = *reinterpret_cast<const uint4*>(bx + (0 * 16 + ng * 4 + j) * 128 + lane * 4);
        #pragma unroll
        for (int kk = 0; kk < 8; ++kk) {
            uint4 a0n, a1n, bfn[4];
            if (kk < 7) {
                a0n = *reinterpret_cast<const uint4*>(ax + ((mg * 2 + 0) * 8 + kk + 1) * 132 + lane * 4);
                a1n = *reinterpret_cast<const uint4*>(ax + ((mg * 2 + 1) * 8 + kk + 1) * 132 + lane * 4);
                #pragma unroll
                for (int j = 0; j < 4; ++j)
                    bfn[j] = *reinterpret_cast<const uint4*>(bx + ((kk + 1) * 16 + ng * 4 + j) * 128 + lane * 4);
            }
            #pragma unroll
            for (int j = 0; j < 4; ++j) {
                mma8(acc[0][2 * j + 0], a0, bf[j].x, bf[j].y);
                mma8(acc[0][2 * j + 1], a0, bf[j].z, bf[j].w);
                mma8(acc[1][2 * j + 0], a1, bf[j].x, bf[j].y);
                mma8(acc[1][2 * j + 1], a1, bf[j].z, bf[j].w);
            }
            if (kk < 7) {
                a0 = a0n; a1 = a1n;
                #pragma unroll
                for (int j = 0; j < 4; ++j) bf[j] = bfn[j];
            }
        }
    }
    // ---- boundary 1: bias+relu+round, store into act A-frag layout ----
    __syncthreads();
    fillB(W2f, 4096, 0); CPA_COMMIT();
    {
        const int offC0 = g * 16 + ((2 * tg) & 3) * 4 + ((tg >= 2) ? 2 : 0);
        const int offC1 = g * 16 + ((2 * tg + 1) & 3) * 4 + ((tg >= 2) ? 2 : 0);
        #pragma unroll
        for (int i = 0; i < 2; ++i) {
            const int mt = mg * 2 + i;
            #pragma unroll
            for (int jj = 0; jj < 8; ++jj) {
                const int kt = ng * 8 + jj;
                const int col0 = ng * 64 + jj * 8 + 2 * tg;
                float* base = sAct + (mt * 32 + kt) * 132;
                const float bA = b1s[col0], bB = b1s[col0 + 1];
                float v0 = f2tf(fmaxf(acc[i][jj][0] + bA, 0.0f));
                float v2 = f2tf(fmaxf(acc[i][jj][2] + bA, 0.0f));
                float v1 = f2tf(fmaxf(acc[i][jj][1] + bB, 0.0f));
                float v3 = f2tf(fmaxf(acc[i][jj][3] + bB, 0.0f));
                *reinterpret_cast<float2*>(base + offC0) = make_float2(v0, v2);
                *reinterpret_cast<float2*>(base + offC1) = make_float2(v1, v3);
            }
        }
    }

    // ============ Layer 2: K=256, 4 slabs ============
    #pragma unroll
    for (int i = 0; i < 2; ++i)
        #pragma unroll
        for (int jj = 0; jj < 8; ++jj)
            #pragma unroll
            for (int e = 0; e < 4; ++e) acc[i][jj][e] = 0.0f;
    for (int s = 0; s < 4; ++s) {
        const int cb = s & 1;
        cpa_wait<0>();
        __syncthreads();                          // publishes boundary-1 stores at s==0
        if (s < 3) { fillB(W2f + (s + 1) * 16384, 4096, cb ^ 1); CPA_COMMIT(); }
        const float* bx = sB + cb * 16384;
        uint4 a0 = *reinterpret_cast<const uint4*>(sAct + ((mg * 2 + 0) * 32 + s * 8 + 0) * 132 + lane * 4);
        uint4 a1 = *reinterpret_cast<const uint4*>(sAct + ((mg * 2 + 1) * 32 + s * 8 + 0) * 132 + lane * 4);
        uint4 bf[4];
        #pragma unroll
        for (int j = 0; j < 4; ++j)
            bf[j] = *reinterpret_cast<const uint4*>(bx + (0 * 16 + ng * 4 + j) * 128 + lane * 4);
        #pragma unroll
        for (int kk = 0; kk < 8; ++kk) {
            uint4 a0n, a1n, bfn[4];
            if (kk < 7) {
                a0n = *reinterpret_cast<const uint4*>(sAct + ((mg * 2 + 0) * 32 + s * 8 + kk + 1) * 132 + lane * 4);
                a1n = *reinterpret_cast<const uint4*>(sAct + ((mg * 2 + 1) * 32 + s * 8 + kk + 1) * 132 + lane * 4);
                #pragma unroll
                for (int j = 0; j < 4; ++j)
                    bfn[j] = *reinterpret_cast<const uint4*>(bx + ((kk + 1) * 16 + ng * 4 + j) * 128 + lane * 4);
            }
            #pragma unroll
            for (int j = 0; j < 4; ++j) {
                mma8(acc[0][2 * j + 0], a0, bf[j].x, bf[j].y);
                mma8(acc[0][2 * j + 1], a0, bf[j].z, bf[j].w);
                mma8(acc[1][2 * j + 0], a1, bf[j].x, bf[j].y);
                mma8(acc[1][2 * j + 1], a1, bf[j].z, bf[j].w);
            }
            if (kk < 7) {
                a0 = a0n; a1 = a1n;
                #pragma unroll
                for (int j = 0; j < 4; ++j) bf[j] = bfn[j];
            }
        }
    }
    // ---- boundary 2: bias+relu+round, store act2 in place ----
    __syncthreads();
    fillB(Wqf, 1024, 0); CPA_COMMIT();
    {
        const int offC0 = g * 16 + ((2 * tg) & 3) * 4 + ((tg >= 2) ? 2 : 0);
        const int offC1 = g * 16 + ((2 * tg + 1) & 3) * 4 + ((tg >= 2) ? 2 : 0);
        #pragma unroll
        for (int i = 0; i < 2; ++i) {
            const int mt = mg * 2 + i;
            #pragma unroll
            for (int jj = 0; jj < 8; ++jj) {
                const int kt = ng * 8 + jj;
                const int col0 = ng * 64 + jj * 8 + 2 * tg;
                float* base = sAct + (mt * 32 + kt) * 132;
                const float bA = b2s[col0], bB = b2s[col0 + 1];
                float v0 = f2tf(fmaxf(acc[i][jj][0] + bA, 0.0f));
                float v2 = f2tf(fmaxf(acc[i][jj][2] + bA, 0.0f));
                float v1 = f2tf(fmaxf(acc[i][jj][1] + bB, 0.0f));
                float v3 = f2tf(fmaxf(acc[i][jj][3] + bB, 0.0f));
                *reinterpret_cast<float2*>(base + offC0) = make_float2(v0, v2);
                *reinterpret_cast<float2*>(base + offC1) = make_float2(v1, v3);
            }
        }
    }

    // ============ Layer 3: K=256, 4 slabs, N=64; warp tile m16 x n32 ============
    const int mi3 = w >> 1, nh3 = w & 1;
    float acc3[4][4];
    #pragma unroll
    for (int jj = 0; jj < 4; ++jj)
        #pragma unroll
        for (int e = 0; e < 4; ++e) acc3[jj][e] = 0.0f;
    for (int s = 0; s < 4; ++s) {
        const int cb = s & 1;
        cpa_wait<0>();
        __syncthreads();                          // publishes boundary-2 stores at s==0
        if (s < 3) { fillB(Wqf + (s + 1) * 4096, 1024, cb ^ 1); CPA_COMMIT(); }
        const float* bx = sB + cb * 16384;
        uint4 a = *reinterpret_cast<const uint4*>(sAct + (mi3 * 32 + s * 8 + 0) * 132 + lane * 4);
        uint4 bf0 = *reinterpret_cast<const uint4*>(bx + (0 * 4 + nh3 * 2 + 0) * 128 + lane * 4);
        uint4 bf1 = *reinterpret_cast<const uint4*>(bx + (0 * 4 + nh3 * 2 + 1) * 128 + lane * 4);
        #pragma unroll
        for (int kk = 0; kk < 8; ++kk) {
            uint4 an, bf0n, bf1n;
            if (kk < 7) {
                an   = *reinterpret_cast<const uint4*>(sAct + (mi3 * 32 + s * 8 + kk + 1) * 132 + lane * 4);
                bf0n = *reinterpret_cast<const uint4*>(bx + ((kk + 1) * 4 + nh3 * 2 + 0) * 128 + lane * 4);
                bf1n = *reinterpret_cast<const uint4*>(bx + ((kk + 1) * 4 + nh3 * 2 + 1) * 128 + lane * 4);
            }
            mma8(acc3[0], a, bf0.x, bf0.y);
            mma8(acc3[1], a, bf0.z, bf0.w);
            mma8(acc3[2], a, bf1.x, bf1.y);
            mma8(acc3[3], a, bf1.z, bf1.w);
            if (kk < 7) { a = an; bf0 = bf0n; bf1 = bf1n; }
        }
    }

    // ---- Epilogue: p = sum tanh(C3 + bq)*Wh ----
    float p = 0.0f;
    #pragma unroll
    for (int nt2 = 0; nt2 < 2; ++nt2)
        #pragma unroll
        for (int h = 0; h < 2; ++h) {
            const int col0 = (nh3 * 2 + nt2) * 16 + h * 8 + 2 * tg;
            const float* d = acc3[nt2 * 2 + h];
            p += tanhf(d[0] + bqs[col0]) * whs[col0];
            p += tanhf(d[2] + bqs[col0]) * whs[col0];
            p += tanhf(d[1] + bqs[col0 + 1]) * whs[col0 + 1];
            p += tanhf(d[3] + bqs[col0 + 1]) * whs[col0 + 1];
        }
    #pragma unroll
    for (int off = 16; off > 0; off >>= 1)
        p += __shfl_down_sync(0xffffffffu, p, off);
    __syncthreads();
    if ((t & 31) == 0) red[w] = p;
    __syncthreads();
    if (t == 0) {
        float s = 0.0f;
        #pragma unroll
        for (int i = 0; i < 8; ++i) s += red[i];
        g_part[blockIdx.x] = s;
        __threadfence();
        unsigned int v = atomicAdd(&g_cnt, 1u);
        flg[0] = (v == NBLK - 1) ? 1.0f : 0.0f;
    }
    __syncthreads();

    if (flg[0] != 0.0f) {
        __threadfence();
        float v = 0.0f;
        if (t < 128) v = g_part[t];
        #pragma unroll
        for (int off = 16; off > 0; off >>= 1)
            v += __shfl_down_sync(0xffffffffu, v, off);
        if ((t & 31) == 0) red[w] = v;
        __syncthreads();
        if (t == 0) {
            out[0] = (red[0] + red[1]) + (red[2] + red[3]) + bh[0];
            g_cnt = 0;
        }
    }
}

extern "C" void kernel_launch(void* const* d_in, const int* in_sizes, int n_in,
                              void* d_out, int out_size)
{
    const float* X  = (const float*)d_in[0];
    const float* W1 = (const float*)d_in[1];
    const float* b1 = (const float*)d_in[2];
    const float* W2 = (const float*)d_in[3];
    const float* b2 = (const float*)d_in[4];
    const float* Wq = (const float*)d_in[5];
    const float* bq = (const float*)d_in[6];
    const float* Wh = (const float*)d_in[7];
    const float* bh = (const float*)d_in[8];

    conv_w<<<208, 256>>>(W1, W2, Wq);
    cudaFuncSetAttribute(fused_mma, cudaFuncAttributeMaxDynamicSharedMemorySize, SMEM_BYTES);
    fused_mma<<<NBLK, THREADS, SMEM_BYTES>>>(X, b1, b2, bq, Wh, bh, (float*)d_out);
}